// round 2
// baseline (speedup 1.0000x reference)
#include <cuda_runtime.h>
#include <cstdint>

#define NN 100000
#define NE 1600000
#define NG 1024
#define HID 128
#define BN_EPS 1e-5f

// ---------------- device scratch (no allocations allowed) ----------------
__device__ int   d_deg[NN];
__device__ int   d_rowstart[NN + 1];
__device__ int   d_cursor[NN];
__device__ int   d_csr_src[NE];
#define SCAN_B 512
#define NSB ((NN + SCAN_B - 1) / SCAN_B)   // 196
__device__ int   d_blocksums[NSB];
__device__ int   d_blockoff[NSB];
__device__ float d_z7[NN * 8];
__device__ float d_A[NN * HID];      // MLP hidden
__device__ float d_z[NN * HID];      // z = h + agg
__device__ float d_xs[NN * 3 * HID]; // jk-cat buffer [NN][384]
__device__ float d_g[NG * 3 * HID];  // pooled graph features
__device__ int   d_gstart[NG + 1];

// ---------------- CSR build ----------------
__global__ void k_zero_deg() {
    int i = blockIdx.x * blockDim.x + threadIdx.x;
    if (i < NN) d_deg[i] = 0;
}

__global__ void k_hist(const int* __restrict__ ei) {
    int e = blockIdx.x * blockDim.x + threadIdx.x;
    if (e < NE) atomicAdd(&d_deg[ei[NE + e]], 1);
}

__global__ void k_scan1() {
    __shared__ int s[SCAN_B];
    int t = threadIdx.x;
    int i = blockIdx.x * SCAN_B + t;
    int v = (i < NN) ? d_deg[i] : 0;
    s[t] = v;
    __syncthreads();
    for (int off = 1; off < SCAN_B; off <<= 1) {
        int x = (t >= off) ? s[t - off] : 0;
        __syncthreads();
        s[t] += x;
        __syncthreads();
    }
    if (i < NN) d_rowstart[i] = s[t];           // inclusive for now
    if (t == SCAN_B - 1) d_blocksums[blockIdx.x] = s[t];
}

__global__ void k_scan2() {
    __shared__ int s[256];
    int t = threadIdx.x;
    int v = (t < NSB) ? d_blocksums[t] : 0;
    s[t] = v;
    __syncthreads();
    for (int off = 1; off < 256; off <<= 1) {
        int x = (t >= off) ? s[t - off] : 0;
        __syncthreads();
        s[t] += x;
        __syncthreads();
    }
    if (t < NSB) d_blockoff[t] = s[t] - v;      // exclusive
}

__global__ void k_scan3() {
    int i = blockIdx.x * blockDim.x + threadIdx.x;
    if (i < NN) {
        int incl = d_rowstart[i];
        int ex = incl - d_deg[i] + d_blockoff[i >> 9];
        d_rowstart[i] = ex;
        d_cursor[i] = ex;
    }
    if (i == 0) d_rowstart[NN] = NE;
}

__global__ void k_fill(const int* __restrict__ ei) {
    int e = blockIdx.x * blockDim.x + threadIdx.x;
    if (e < NE) {
        int dst = ei[NE + e];
        int pos = atomicAdd(&d_cursor[dst], 1);
        d_csr_src[pos] = ei[e];
    }
}

// ---------------- layer 0: 7-dim aggregation, z7 = x + agg ----------------
__global__ void k_agg7(const float* __restrict__ x) {
    int n = blockIdx.x * blockDim.x + threadIdx.x;
    if (n >= NN) return;
    float a[7];
#pragma unroll
    for (int j = 0; j < 7; j++) a[j] = x[n * 7 + j];
    int s = d_rowstart[n], e = d_rowstart[n + 1];
    for (int i = s; i < e; i++) {
        int src = d_csr_src[i];
        const float* xp = x + src * 7;
#pragma unroll
        for (int j = 0; j < 7; j++) a[j] += __ldg(xp + j);
    }
#pragma unroll
    for (int j = 0; j < 7; j++) d_z7[n * 8 + j] = a[j];
    d_z7[n * 8 + 7] = 0.0f;
}

// lin0: A = relu(z7 @ w1_0 + b1_0), w1_0 is [7][128]
__global__ void k_lin0(const float* __restrict__ w1, const float* __restrict__ b1) {
    __shared__ float ws[7 * 128 + 128];
    int tid = threadIdx.x;
    for (int i = tid; i < 7 * 128 + 128; i += 256)
        ws[i] = (i < 7 * 128) ? w1[i] : b1[i - 7 * 128];
    __syncthreads();
    int gt = blockIdx.x * 256 + tid;
    int node = gt >> 5;
    int cg = gt & 31;
    if (node >= NN) return;
    float a[7];
#pragma unroll
    for (int j = 0; j < 7; j++) a[j] = d_z7[node * 8 + j];
    const float* bb = ws + 7 * 128;
    float4 acc = *(const float4*)(bb + cg * 4);
#pragma unroll
    for (int j = 0; j < 7; j++) {
        float4 w = *(const float4*)(ws + j * 128 + cg * 4);
        acc.x += a[j] * w.x;
        acc.y += a[j] * w.y;
        acc.z += a[j] * w.z;
        acc.w += a[j] * w.w;
    }
    acc.x = fmaxf(acc.x, 0.f); acc.y = fmaxf(acc.y, 0.f);
    acc.z = fmaxf(acc.z, 0.f); acc.w = fmaxf(acc.w, 0.f);
    *(float4*)(d_A + node * HID + cg * 4) = acc;
}

// ---------------- 128-dim aggregation: z = h + sum_{src} h[src] ----------------
__global__ void k_agg128(const float* __restrict__ h, int ldh) {
    int gt = blockIdx.x * blockDim.x + threadIdx.x;
    int n = gt >> 5;
    int lane = gt & 31;
    if (n >= NN) return;
    float4 acc = *(const float4*)(h + (size_t)n * ldh + lane * 4);
    int s = d_rowstart[n], e = d_rowstart[n + 1];
    int i = s;
    for (; i + 1 < e; i += 2) {
        int s0 = d_csr_src[i];
        int s1 = d_csr_src[i + 1];
        float4 v0 = *(const float4*)(h + (size_t)s0 * ldh + lane * 4);
        float4 v1 = *(const float4*)(h + (size_t)s1 * ldh + lane * 4);
        acc.x += v0.x; acc.y += v0.y; acc.z += v0.z; acc.w += v0.w;
        acc.x += v1.x; acc.y += v1.y; acc.z += v1.z; acc.w += v1.w;
    }
    if (i < e) {
        int s0 = d_csr_src[i];
        float4 v0 = *(const float4*)(h + (size_t)s0 * ldh + lane * 4);
        acc.x += v0.x; acc.y += v0.y; acc.z += v0.z; acc.w += v0.w;
    }
    *(float4*)(d_z + n * HID + lane * 4) = acc;
}

// ---------------- main GEMM: C = relu(A[M,128] @ W[128,128] + b) ----------------
// BM=64, BN=128 (full), BK=128 (full). 256 threads, 8x4 register tile.
#define GEMM_BM 64
__global__ void __launch_bounds__(256)
k_gemm(const float* __restrict__ A, int lda,
       const float* __restrict__ W, const float* __restrict__ bias,
       float* __restrict__ C, int ldc, int M) {
    extern __shared__ float sm[];
    float* As = sm;              // [128][64], k-major
    float* Ws = sm + 128 * 64;   // [128][128]
    int tid = threadIdx.x;
    int m0 = blockIdx.x * GEMM_BM;

    // load A tile transposed
    int r = tid & 63;
    int q0 = tid >> 6;  // 0..3
#pragma unroll
    for (int j = 0; j < 8; j++) {
        int q = q0 + 4 * j;
        int k = q * 4;
        int m = m0 + r;
        float4 v = make_float4(0.f, 0.f, 0.f, 0.f);
        if (m < M) v = *(const float4*)(A + (size_t)m * lda + k);
        As[(k + 0) * 64 + r] = v.x;
        As[(k + 1) * 64 + r] = v.y;
        As[(k + 2) * 64 + r] = v.z;
        As[(k + 3) * 64 + r] = v.w;
    }
    // load W tile
    const float4* Wv = (const float4*)W;
    float4* Wsv = (float4*)Ws;
#pragma unroll
    for (int j = 0; j < 16; j++) Wsv[tid + 256 * j] = Wv[tid + 256 * j];
    __syncthreads();

    int tx = tid & 31, ty = tid >> 5;
    float acc[8][4];
#pragma unroll
    for (int i = 0; i < 8; i++)
#pragma unroll
        for (int jj = 0; jj < 4; jj++) acc[i][jj] = 0.f;

    const float* Ab = As + ty * 8;
    const float* Wb = Ws + tx * 4;
#pragma unroll 4
    for (int k = 0; k < 128; k++) {
        float4 a0 = *(const float4*)(Ab + k * 64);
        float4 a1 = *(const float4*)(Ab + k * 64 + 4);
        float4 w = *(const float4*)(Wb + k * 128);
        float av[8] = {a0.x, a0.y, a0.z, a0.w, a1.x, a1.y, a1.z, a1.w};
        float wv[4] = {w.x, w.y, w.z, w.w};
#pragma unroll
        for (int i = 0; i < 8; i++)
#pragma unroll
            for (int jj = 0; jj < 4; jj++) acc[i][jj] += av[i] * wv[jj];
    }

    float4 b = __ldg((const float4*)(bias + tx * 4));
#pragma unroll
    for (int i = 0; i < 8; i++) {
        int m = m0 + ty * 8 + i;
        if (m < M) {
            float4 o;
            o.x = fmaxf(acc[i][0] + b.x, 0.f);
            o.y = fmaxf(acc[i][1] + b.y, 0.f);
            o.z = fmaxf(acc[i][2] + b.z, 0.f);
            o.w = fmaxf(acc[i][3] + b.w, 0.f);
            *(float4*)(C + (size_t)m * ldc + tx * 4) = o;
        }
    }
}

// ---------------- pooling ----------------
__global__ void k_bounds(const int* __restrict__ batch) {
    int i = blockIdx.x * blockDim.x + threadIdx.x;
    if (i >= NN) return;
    int b = batch[i];
    int pb = (i == 0) ? -1 : batch[i - 1];
    for (int g = pb + 1; g <= b; g++) d_gstart[g] = i;
    if (i == NN - 1)
        for (int g = b + 1; g <= NG; g++) d_gstart[g] = NN;
}

__global__ void k_pool() {
    int g = blockIdx.x;
    int t = threadIdx.x;  // 128 threads
    int s = d_gstart[g], e = d_gstart[g + 1];
    float a0 = 0.f, a1 = 0.f, a2 = 0.f;
    for (int n = s; n < e; n++) {
        const float* row = d_xs + (size_t)n * 384;
        a0 += row[t];
        a1 += row[128 + t];
        a2 += row[256 + t];
    }
    d_g[g * 384 + t] = a0;
    d_g[g * 384 + 128 + t] = a1;
    d_g[g * 384 + 256 + t] = a2;
}

// ---------------- classifier: 16 graphs per block ----------------
__global__ void __launch_bounds__(256)
k_clf(const float* __restrict__ w1, const float* __restrict__ b1,
      const float* __restrict__ w2, const float* __restrict__ b2,
      const float* __restrict__ gamma, const float* __restrict__ beta,
      const float* __restrict__ mean, const float* __restrict__ var,
      float* __restrict__ out) {
    __shared__ float sg[16 * 384];
    __shared__ float sz[16 * 256];
    int tid = threadIdx.x;
    int g0 = blockIdx.x * 16;
    for (int i = tid; i < 16 * 384; i += 256) sg[i] = d_g[g0 * 384 + i];
    __syncthreads();
    float acc[16];
#pragma unroll
    for (int gi = 0; gi < 16; gi++) acc[gi] = 0.f;
    for (int k = 0; k < 384; k++) {
        float w = __ldg(w1 + k * 256 + tid);
#pragma unroll
        for (int gi = 0; gi < 16; gi++) acc[gi] += sg[gi * 384 + k] * w;
    }
    float bb = __ldg(b1 + tid);
    float mu = __ldg(mean + tid);
    float iv = rsqrtf(__ldg(var + tid) + BN_EPS);
    float ga = __ldg(gamma + tid);
    float be = __ldg(beta + tid);
#pragma unroll
    for (int gi = 0; gi < 16; gi++) {
        float zv = acc[gi] + bb;
        zv = (zv - mu) * iv * ga + be;
        sz[gi * 256 + tid] = fmaxf(zv, 0.f);
    }
    __syncthreads();
    if (tid < 32) {
        int gi = tid >> 1, c = tid & 1;
        float s = __ldg(b2 + c);
        for (int k = 0; k < 256; k++) s += sz[gi * 256 + k] * __ldg(w2 + k * 2 + c);
        out[(g0 + gi) * 2 + c] = s;
    }
}

// ---------------- launch ----------------
extern "C" void kernel_launch(void* const* d_in, const int* in_sizes, int n_in,
                              void* d_out, int out_size) {
    const float* x   = (const float*)d_in[0];
    const int*   ei  = (const int*)d_in[1];
    const int*   bat = (const int*)d_in[2];
    const float* w1_0 = (const float*)d_in[3];
    const float* b1_0 = (const float*)d_in[4];
    const float* w2_0 = (const float*)d_in[5];
    const float* b2_0 = (const float*)d_in[6];
    const float* w1_1 = (const float*)d_in[7];
    const float* b1_1 = (const float*)d_in[8];
    const float* w2_1 = (const float*)d_in[9];
    const float* b2_1 = (const float*)d_in[10];
    const float* w1_2 = (const float*)d_in[11];
    const float* b1_2 = (const float*)d_in[12];
    const float* w2_2 = (const float*)d_in[13];
    const float* b2_2 = (const float*)d_in[14];
    const float* cw1 = (const float*)d_in[15];
    const float* cb1 = (const float*)d_in[16];
    const float* cw2 = (const float*)d_in[17];
    const float* cb2 = (const float*)d_in[18];
    const float* bng = (const float*)d_in[19];
    const float* bnb = (const float*)d_in[20];
    const float* bnm = (const float*)d_in[21];
    const float* bnv = (const float*)d_in[22];
    float* out = (float*)d_out;

    static bool attr_set = false;
    size_t gemm_smem = (128 * 64 + 128 * 128) * sizeof(float);  // 96 KB
    cudaFuncSetAttribute(k_gemm, cudaFuncAttributeMaxDynamicSharedMemorySize,
                         (int)gemm_smem);
    (void)attr_set;

    float* xs0 = nullptr; // symbol arithmetic done device-side via globals; use helper below
    // we can't take device-global addresses on host without cudaGetSymbolAddress;
    // instead pass slice offsets as the output-pointer argument is needed only for gemm C.
    // Use cudaGetSymbolAddress (pure lookup, capture-safe).
    static float* p_xs = nullptr;
    static float* p_A = nullptr;
    static float* p_z = nullptr;
    if (!p_xs) {
        void* tmp;
        cudaGetSymbolAddress(&tmp, d_xs); p_xs = (float*)tmp;
        cudaGetSymbolAddress(&tmp, d_A);  p_A = (float*)tmp;
        cudaGetSymbolAddress(&tmp, d_z);  p_z = (float*)tmp;
    }

    int tb = 256;
    // CSR build
    k_zero_deg<<<(NN + tb - 1) / tb, tb>>>();
    k_hist<<<(NE + tb - 1) / tb, tb>>>(ei);
    k_scan1<<<NSB, SCAN_B>>>();
    k_scan2<<<1, 256>>>();
    k_scan3<<<(NN + tb - 1) / tb, tb>>>();
    k_fill<<<(NE + tb - 1) / tb, tb>>>(ei);

    int gemm_grid = (NN + GEMM_BM - 1) / GEMM_BM;
    int agg_grid = (NN * 32 + tb - 1) / tb;

    // layer 0
    k_agg7<<<(NN + tb - 1) / tb, tb>>>(x);
    k_lin0<<<agg_grid, tb>>>(w1_0, b1_0);
    k_gemm<<<gemm_grid, tb, gemm_smem>>>(p_A, HID, w2_0, b2_0, p_xs + 0, 384, NN);
    // layer 1
    k_agg128<<<agg_grid, tb>>>(p_xs + 0, 384);
    k_gemm<<<gemm_grid, tb, gemm_smem>>>(p_z, HID, w1_1, b1_1, p_A, HID, NN);
    k_gemm<<<gemm_grid, tb, gemm_smem>>>(p_A, HID, w2_1, b2_1, p_xs + 128, 384, NN);
    // layer 2
    k_agg128<<<agg_grid, tb>>>(p_xs + 128, 384);
    k_gemm<<<gemm_grid, tb, gemm_smem>>>(p_z, HID, w1_2, b1_2, p_A, HID, NN);
    k_gemm<<<gemm_grid, tb, gemm_smem>>>(p_A, HID, w2_2, b2_2, p_xs + 256, 384, NN);
    // pool + classifier
    k_bounds<<<(NN + tb - 1) / tb, tb>>>(bat);
    k_pool<<<NG, 128>>>();
    k_clf<<<NG / 16, 256>>>(cw1, cb1, cw2, cb2, bng, bnb, bnm, bnv, out);
}

// round 3
// speedup vs baseline: 1.4466x; 1.4466x over previous
#include <cuda_runtime.h>
#include <cstdint>

#define NN 100000
#define NE 1600000
#define NG 1024
#define HID 128
#define BN_EPS 1e-5f

// ---------------- device scratch (no allocations allowed) ----------------
__device__ int   d_deg[NN];
__device__ int   d_rowstart[NN + 1];
__device__ int   d_cursor[NN];
__device__ int   d_csr_src[NE];
#define SCAN_B 512
#define NSB ((NN + SCAN_B - 1) / SCAN_B)   // 196
__device__ int   d_blocksums[NSB];
__device__ int   d_blockoff[NSB];
__device__ float d_z7[NN * 8];
__device__ float d_A[NN * HID];      // MLP hidden
__device__ float d_z[NN * HID];      // z = h + agg
__device__ float d_xs[NN * 3 * HID]; // jk-cat buffer [NN][384]
__device__ float d_g[NG * 3 * HID];  // pooled graph features
__device__ int   d_gstart[NG + 1];

// ---------------- CSR build ----------------
__global__ void k_zero_deg() {
    int i = blockIdx.x * blockDim.x + threadIdx.x;
    if (i < NN) d_deg[i] = 0;
}

__global__ void k_hist(const int* __restrict__ ei) {
    int e = blockIdx.x * blockDim.x + threadIdx.x;
    if (e < NE) atomicAdd(&d_deg[ei[NE + e]], 1);
}

__global__ void k_scan1() {
    __shared__ int s[SCAN_B];
    int t = threadIdx.x;
    int i = blockIdx.x * SCAN_B + t;
    int v = (i < NN) ? d_deg[i] : 0;
    s[t] = v;
    __syncthreads();
    for (int off = 1; off < SCAN_B; off <<= 1) {
        int x = (t >= off) ? s[t - off] : 0;
        __syncthreads();
        s[t] += x;
        __syncthreads();
    }
    if (i < NN) d_rowstart[i] = s[t];           // inclusive for now
    if (t == SCAN_B - 1) d_blocksums[blockIdx.x] = s[t];
}

__global__ void k_scan2() {
    __shared__ int s[256];
    int t = threadIdx.x;
    int v = (t < NSB) ? d_blocksums[t] : 0;
    s[t] = v;
    __syncthreads();
    for (int off = 1; off < 256; off <<= 1) {
        int x = (t >= off) ? s[t - off] : 0;
        __syncthreads();
        s[t] += x;
        __syncthreads();
    }
    if (t < NSB) d_blockoff[t] = s[t] - v;      // exclusive
}

__global__ void k_scan3() {
    int i = blockIdx.x * blockDim.x + threadIdx.x;
    if (i < NN) {
        int incl = d_rowstart[i];
        int ex = incl - d_deg[i] + d_blockoff[i >> 9];
        d_rowstart[i] = ex;
        d_cursor[i] = ex;
    }
    if (i == 0) d_rowstart[NN] = NE;
}

__global__ void k_fill(const int* __restrict__ ei) {
    int e = blockIdx.x * blockDim.x + threadIdx.x;
    if (e < NE) {
        int dst = ei[NE + e];
        int pos = atomicAdd(&d_cursor[dst], 1);
        d_csr_src[pos] = ei[e];
    }
}

// ---------------- layer 0: 7-dim aggregation, z7 = x + agg ----------------
__global__ void k_agg7(const float* __restrict__ x) {
    int n = blockIdx.x * blockDim.x + threadIdx.x;
    if (n >= NN) return;
    float a[7];
#pragma unroll
    for (int j = 0; j < 7; j++) a[j] = x[n * 7 + j];
    int s = d_rowstart[n], e = d_rowstart[n + 1];
    for (int i = s; i < e; i++) {
        int src = d_csr_src[i];
        const float* xp = x + src * 7;
#pragma unroll
        for (int j = 0; j < 7; j++) a[j] += __ldg(xp + j);
    }
#pragma unroll
    for (int j = 0; j < 7; j++) d_z7[n * 8 + j] = a[j];
    d_z7[n * 8 + 7] = 0.0f;
}

// lin0: A = relu(z7 @ w1_0 + b1_0), w1_0 is [7][128]
__global__ void k_lin0(const float* __restrict__ w1, const float* __restrict__ b1) {
    __shared__ float ws[7 * 128 + 128];
    int tid = threadIdx.x;
    for (int i = tid; i < 7 * 128 + 128; i += 256)
        ws[i] = (i < 7 * 128) ? w1[i] : b1[i - 7 * 128];
    __syncthreads();
    int gt = blockIdx.x * 256 + tid;
    int node = gt >> 5;
    int cg = gt & 31;
    if (node >= NN) return;
    float a[7];
#pragma unroll
    for (int j = 0; j < 7; j++) a[j] = d_z7[node * 8 + j];
    const float* bb = ws + 7 * 128;
    float4 acc = *(const float4*)(bb + cg * 4);
#pragma unroll
    for (int j = 0; j < 7; j++) {
        float4 w = *(const float4*)(ws + j * 128 + cg * 4);
        acc.x += a[j] * w.x;
        acc.y += a[j] * w.y;
        acc.z += a[j] * w.z;
        acc.w += a[j] * w.w;
    }
    acc.x = fmaxf(acc.x, 0.f); acc.y = fmaxf(acc.y, 0.f);
    acc.z = fmaxf(acc.z, 0.f); acc.w = fmaxf(acc.w, 0.f);
    *(float4*)(d_A + node * HID + cg * 4) = acc;
}

// ---------------- 128-dim aggregation: z = h + sum_{src} h[src] ----------------
__global__ void k_agg128(const float* __restrict__ h, int ldh) {
    int gt = blockIdx.x * blockDim.x + threadIdx.x;
    int n = gt >> 5;
    int lane = gt & 31;
    if (n >= NN) return;
    float4 acc = *(const float4*)(h + (size_t)n * ldh + lane * 4);
    int s = d_rowstart[n], e = d_rowstart[n + 1];
    int i = s;
    for (; i + 1 < e; i += 2) {
        int s0 = d_csr_src[i];
        int s1 = d_csr_src[i + 1];
        float4 v0 = *(const float4*)(h + (size_t)s0 * ldh + lane * 4);
        float4 v1 = *(const float4*)(h + (size_t)s1 * ldh + lane * 4);
        acc.x += v0.x; acc.y += v0.y; acc.z += v0.z; acc.w += v0.w;
        acc.x += v1.x; acc.y += v1.y; acc.z += v1.z; acc.w += v1.w;
    }
    if (i < e) {
        int s0 = d_csr_src[i];
        float4 v0 = *(const float4*)(h + (size_t)s0 * ldh + lane * 4);
        acc.x += v0.x; acc.y += v0.y; acc.z += v0.z; acc.w += v0.w;
    }
    *(float4*)(d_z + n * HID + lane * 4) = acc;
}

// ---------------- tf32 tensor-core GEMM ----------------
// C[M,128] = relu(A[M,128] @ W[128,128] + bias), via mma.sync.m16n8k8 tf32
// BM=128, BN=128, K=128 fully smem-resident. 256 threads = 8 warps (4m x 2n),
// each warp computes 32x64 via 2(m) x 8(n) x 16(k) mma chain.
#define ASTRIDE 132   // conflict-free for A-frag pattern
#define WSTRIDE 136   // conflict-free for B-frag pattern
#define GEMM_SMEM ((128 * ASTRIDE + 128 * WSTRIDE) * 4)

__device__ __forceinline__ float tf32r(float x) {
    asm("cvt.rna.tf32.f32 %0, %0;" : "+f"(x));
    return x;
}

__global__ void __launch_bounds__(256)
k_gemm_tc(const float* __restrict__ A, int lda,
          const float* __restrict__ W, const float* __restrict__ bias,
          float* __restrict__ C, int ldc, int M) {
    extern __shared__ float sm[];
    float* As = sm;                    // [128][ASTRIDE]
    float* Ws = sm + 128 * ASTRIDE;    // [128][WSTRIDE]
    int tid = threadIdx.x;
    int m0 = blockIdx.x * 128;

    // load + tf32-round A tile (row-major, padded)
#pragma unroll
    for (int idx = tid; idx < 128 * 32; idx += 256) {
        int r = idx >> 5, q = idx & 31;
        int m = m0 + r;
        float4 v = make_float4(0.f, 0.f, 0.f, 0.f);
        if (m < M) v = *(const float4*)(A + (size_t)m * lda + q * 4);
        float* p = As + r * ASTRIDE + q * 4;
        p[0] = tf32r(v.x); p[1] = tf32r(v.y);
        p[2] = tf32r(v.z); p[3] = tf32r(v.w);
    }
    // load + tf32-round W tile [k][n]
#pragma unroll
    for (int idx = tid; idx < 128 * 32; idx += 256) {
        int r = idx >> 5, q = idx & 31;
        float4 v = *(const float4*)(W + r * 128 + q * 4);
        float* p = Ws + r * WSTRIDE + q * 4;
        p[0] = tf32r(v.x); p[1] = tf32r(v.y);
        p[2] = tf32r(v.z); p[3] = tf32r(v.w);
    }
    __syncthreads();

    int lane = tid & 31;
    int warp = tid >> 5;
    int wm = (warp >> 1) * 32;   // warp m offset
    int wn = (warp & 1) * 64;    // warp n offset
    int r = lane >> 2;           // 0..7
    int c = lane & 3;            // 0..3

    float acc[2][8][4];
#pragma unroll
    for (int mi = 0; mi < 2; mi++)
#pragma unroll
        for (int ni = 0; ni < 8; ni++)
#pragma unroll
            for (int j = 0; j < 4; j++) acc[mi][ni][j] = 0.f;

#pragma unroll
    for (int kt = 0; kt < 16; kt++) {
        int k0 = kt * 8;
        uint32_t a[2][4];
#pragma unroll
        for (int mi = 0; mi < 2; mi++) {
            const float* ap = As + (wm + mi * 16) * ASTRIDE + k0;
            a[mi][0] = __float_as_uint(ap[r * ASTRIDE + c]);
            a[mi][1] = __float_as_uint(ap[(r + 8) * ASTRIDE + c]);
            a[mi][2] = __float_as_uint(ap[r * ASTRIDE + c + 4]);
            a[mi][3] = __float_as_uint(ap[(r + 8) * ASTRIDE + c + 4]);
        }
        uint32_t b[8][2];
#pragma unroll
        for (int ni = 0; ni < 8; ni++) {
            const float* bp = Ws + k0 * WSTRIDE + wn + ni * 8 + r;
            b[ni][0] = __float_as_uint(bp[c * WSTRIDE]);
            b[ni][1] = __float_as_uint(bp[(c + 4) * WSTRIDE]);
        }
#pragma unroll
        for (int mi = 0; mi < 2; mi++)
#pragma unroll
            for (int ni = 0; ni < 8; ni++) {
                asm volatile(
                    "mma.sync.aligned.m16n8k8.row.col.f32.tf32.tf32.f32 "
                    "{%0,%1,%2,%3}, {%4,%5,%6,%7}, {%8,%9}, {%0,%1,%2,%3};"
                    : "+f"(acc[mi][ni][0]), "+f"(acc[mi][ni][1]),
                      "+f"(acc[mi][ni][2]), "+f"(acc[mi][ni][3])
                    : "r"(a[mi][0]), "r"(a[mi][1]), "r"(a[mi][2]), "r"(a[mi][3]),
                      "r"(b[ni][0]), "r"(b[ni][1]));
            }
    }

    // epilogue: bias + relu, write float2 pairs
#pragma unroll
    for (int mi = 0; mi < 2; mi++) {
        int row0 = m0 + wm + mi * 16 + r;
#pragma unroll
        for (int ni = 0; ni < 8; ni++) {
            int col = wn + ni * 8 + c * 2;
            float bx = __ldg(bias + col);
            float by = __ldg(bias + col + 1);
            if (row0 < M) {
                float2 o;
                o.x = fmaxf(acc[mi][ni][0] + bx, 0.f);
                o.y = fmaxf(acc[mi][ni][1] + by, 0.f);
                *(float2*)(C + (size_t)row0 * ldc + col) = o;
            }
            int row1 = row0 + 8;
            if (row1 < M) {
                float2 o;
                o.x = fmaxf(acc[mi][ni][2] + bx, 0.f);
                o.y = fmaxf(acc[mi][ni][3] + by, 0.f);
                *(float2*)(C + (size_t)row1 * ldc + col) = o;
            }
        }
    }
}

// ---------------- pooling ----------------
__global__ void k_bounds(const int* __restrict__ batch) {
    int i = blockIdx.x * blockDim.x + threadIdx.x;
    if (i >= NN) return;
    int b = batch[i];
    int pb = (i == 0) ? -1 : batch[i - 1];
    for (int g = pb + 1; g <= b; g++) d_gstart[g] = i;
    if (i == NN - 1)
        for (int g = b + 1; g <= NG; g++) d_gstart[g] = NN;
}

__global__ void k_pool() {
    int g = blockIdx.x;
    int t = threadIdx.x;  // 128 threads
    int s = d_gstart[g], e = d_gstart[g + 1];
    float a0 = 0.f, a1 = 0.f, a2 = 0.f;
    for (int n = s; n < e; n++) {
        const float* row = d_xs + (size_t)n * 384;
        a0 += row[t];
        a1 += row[128 + t];
        a2 += row[256 + t];
    }
    d_g[g * 384 + t] = a0;
    d_g[g * 384 + 128 + t] = a1;
    d_g[g * 384 + 256 + t] = a2;
}

// ---------------- classifier: 16 graphs per block ----------------
__global__ void __launch_bounds__(256)
k_clf(const float* __restrict__ w1, const float* __restrict__ b1,
      const float* __restrict__ w2, const float* __restrict__ b2,
      const float* __restrict__ gamma, const float* __restrict__ beta,
      const float* __restrict__ mean, const float* __restrict__ var,
      float* __restrict__ out) {
    __shared__ float sg[16 * 384];
    __shared__ float sz[16 * 256];
    int tid = threadIdx.x;
    int g0 = blockIdx.x * 16;
    for (int i = tid; i < 16 * 384; i += 256) sg[i] = d_g[g0 * 384 + i];
    __syncthreads();
    float acc[16];
#pragma unroll
    for (int gi = 0; gi < 16; gi++) acc[gi] = 0.f;
    for (int k = 0; k < 384; k++) {
        float w = __ldg(w1 + k * 256 + tid);
#pragma unroll
        for (int gi = 0; gi < 16; gi++) acc[gi] += sg[gi * 384 + k] * w;
    }
    float bb = __ldg(b1 + tid);
    float mu = __ldg(mean + tid);
    float iv = rsqrtf(__ldg(var + tid) + BN_EPS);
    float ga = __ldg(gamma + tid);
    float be = __ldg(beta + tid);
#pragma unroll
    for (int gi = 0; gi < 16; gi++) {
        float zv = acc[gi] + bb;
        zv = (zv - mu) * iv * ga + be;
        sz[gi * 256 + tid] = fmaxf(zv, 0.f);
    }
    __syncthreads();
    if (tid < 32) {
        int gi = tid >> 1, c = tid & 1;
        float s = __ldg(b2 + c);
        for (int k = 0; k < 256; k++) s += sz[gi * 256 + k] * __ldg(w2 + k * 2 + c);
        out[(g0 + gi) * 2 + c] = s;
    }
}

// ---------------- launch ----------------
extern "C" void kernel_launch(void* const* d_in, const int* in_sizes, int n_in,
                              void* d_out, int out_size) {
    const float* x   = (const float*)d_in[0];
    const int*   ei  = (const int*)d_in[1];
    const int*   bat = (const int*)d_in[2];
    const float* w1_0 = (const float*)d_in[3];
    const float* b1_0 = (const float*)d_in[4];
    const float* w2_0 = (const float*)d_in[5];
    const float* b2_0 = (const float*)d_in[6];
    const float* w1_1 = (const float*)d_in[7];
    const float* b1_1 = (const float*)d_in[8];
    const float* w2_1 = (const float*)d_in[9];
    const float* b2_1 = (const float*)d_in[10];
    const float* w1_2 = (const float*)d_in[11];
    const float* b1_2 = (const float*)d_in[12];
    const float* w2_2 = (const float*)d_in[13];
    const float* b2_2 = (const float*)d_in[14];
    const float* cw1 = (const float*)d_in[15];
    const float* cb1 = (const float*)d_in[16];
    const float* cw2 = (const float*)d_in[17];
    const float* cb2 = (const float*)d_in[18];
    const float* bng = (const float*)d_in[19];
    const float* bnb = (const float*)d_in[20];
    const float* bnm = (const float*)d_in[21];
    const float* bnv = (const float*)d_in[22];
    float* out = (float*)d_out;

    cudaFuncSetAttribute(k_gemm_tc, cudaFuncAttributeMaxDynamicSharedMemorySize,
                         GEMM_SMEM);

    static float* p_xs = nullptr;
    static float* p_A = nullptr;
    static float* p_z = nullptr;
    if (!p_xs) {
        void* tmp;
        cudaGetSymbolAddress(&tmp, d_xs); p_xs = (float*)tmp;
        cudaGetSymbolAddress(&tmp, d_A);  p_A = (float*)tmp;
        cudaGetSymbolAddress(&tmp, d_z);  p_z = (float*)tmp;
    }

    int tb = 256;
    // CSR build
    k_zero_deg<<<(NN + tb - 1) / tb, tb>>>();
    k_hist<<<(NE + tb - 1) / tb, tb>>>(ei);
    k_scan1<<<NSB, SCAN_B>>>();
    k_scan2<<<1, 256>>>();
    k_scan3<<<(NN + tb - 1) / tb, tb>>>();
    k_fill<<<(NE + tb - 1) / tb, tb>>>(ei);

    int gemm_grid = (NN + 127) / 128;
    int agg_grid = (NN * 32 + tb - 1) / tb;

    // layer 0
    k_agg7<<<(NN + tb - 1) / tb, tb>>>(x);
    k_lin0<<<agg_grid, tb>>>(w1_0, b1_0);
    k_gemm_tc<<<gemm_grid, tb, GEMM_SMEM>>>(p_A, HID, w2_0, b2_0, p_xs + 0, 384, NN);
    // layer 1
    k_agg128<<<agg_grid, tb>>>(p_xs + 0, 384);
    k_gemm_tc<<<gemm_grid, tb, GEMM_SMEM>>>(p_z, HID, w1_1, b1_1, p_A, HID, NN);
    k_gemm_tc<<<gemm_grid, tb, GEMM_SMEM>>>(p_A, HID, w2_1, b2_1, p_xs + 128, 384, NN);
    // layer 2
    k_agg128<<<agg_grid, tb>>>(p_xs + 128, 384);
    k_gemm_tc<<<gemm_grid, tb, GEMM_SMEM>>>(p_z, HID, w1_2, b1_2, p_A, HID, NN);
    k_gemm_tc<<<gemm_grid, tb, GEMM_SMEM>>>(p_A, HID, w2_2, b2_2, p_xs + 256, 384, NN);
    // pool + classifier
    k_bounds<<<(NN + tb - 1) / tb, tb>>>(bat);
    k_pool<<<NG, 128>>>();
    k_clf<<<NG / 16, 256>>>(cw1, cb1, cw2, cb2, bng, bnb, bnm, bnv, out);
}